// round 4
// baseline (speedup 1.0000x reference)
#include <cuda_runtime.h>
#include <math.h>
#include <stdint.h>

#define NB    2
#define NC    128
#define NH    512
#define NW    512
#define NWIN  4096      // 64 x 64 windows
#define NWF   1228      // int(4096 * 0.3)
#define NSEL  (NB*NWF)  // 2456
#define WINSZ 64
#define SCALE 0.08838834764831845f   // 128^-0.5

// ---------------- scratch (static device globals; allocation-free) ----------
__device__ float    g_score[NB*NWIN];
__device__ int      g_sel[NB*NWF];
__device__ int      g_cnt[NB];
__device__ float    g_gx[NB*NC*64];          // pooled features [b][c][cell]
__device__ float    g_kv[2*NB*64*NC];        // k then v: [b][p][c]
__device__ uint32_t g_wtf[6*128*128];        // tf32-rounded weights
// offsets into g_wtf (in 128x128 matrices): 0=qgw, 1=linner0, 2=q2, 3=k2, 4=v2, 5=proj
#define WT_QG   (0*16384)
#define WT_LIN  (1*16384)
#define WT_Q2   (2*16384)
#define WT_K2   (3*16384)
#define WT_V2   (4*16384)
#define WT_PROJ (5*16384)

// ---------------- tf32 helpers ----------------------------------------------
__device__ __forceinline__ uint32_t f2tf(float f) {
    uint32_t r;
    asm("cvt.rna.tf32.f32 %0, %1;" : "=r"(r) : "f"(f));
    return r;
}

__device__ __forceinline__ void mma_tf32(float& c0, float& c1, float& c2, float& c3,
                                         uint32_t a0, uint32_t a1, uint32_t a2, uint32_t a3,
                                         uint32_t b0, uint32_t b1) {
    asm volatile("mma.sync.aligned.m16n8k8.row.col.f32.tf32.tf32.f32 "
                 "{%0,%1,%2,%3}, {%4,%5,%6,%7}, {%8,%9}, {%0,%1,%2,%3};"
                 : "+f"(c0), "+f"(c1), "+f"(c2), "+f"(c3)
                 : "r"(a0), "r"(a1), "r"(a2), "r"(a3), "r"(b0), "r"(b1));
}

// ---------------- weight prep: fp32 -> tf32 bits ----------------------------
__global__ void wprep_kernel(const float* __restrict__ qgw, const float* __restrict__ lw,
                             const float* __restrict__ qkvw, const float* __restrict__ pw) {
    int i = blockIdx.x * 256 + threadIdx.x;           // 98304 total
    float v;
    if      (i < 16384) v = qgw[i];
    else if (i < 32768) v = lw[i - 16384];
    else if (i < 81920) v = qkvw[i - 32768];
    else                v = pw[i - 81920];
    g_wtf[i] = f2tf(v);
}

// ---------------- window scores (double accumulation, rounded to fp32) -----
__global__ void scores_kernel(const float* __restrict__ unc) {
    if (blockIdx.x == 0 && threadIdx.x < NB) g_cnt[threadIdx.x] = 0;
    int gw   = blockIdx.x * 8 + (threadIdx.x >> 5);
    int lane = threadIdx.x & 31;
    if (gw >= NB*NWIN) return;
    int b = gw / NWIN, w = gw % NWIN;
    int wh = w >> 6, ww = w & 63;
    const float* base = unc + ((size_t)b*NH + wh*8)*NW + ww*8;
    int r0 = lane >> 3, c0 = lane & 7;
    double s = (double)base[r0*NW + c0] + (double)base[(r0+4)*NW + c0];
    #pragma unroll
    for (int o = 16; o; o >>= 1) s += __shfl_down_sync(0xffffffffu, s, o);
    if (lane == 0) g_score[gw] = (float)(s * (1.0/64.0));
}

// ---------------- stable top-k via rank (score desc, index asc) ------------
__global__ void select_kernel() {
    __shared__ float s_sc[NWIN];
    int b = blockIdx.x >> 2;
    int part = blockIdx.x & 3;
    const float* sc = g_score + b*NWIN;
    for (int i = threadIdx.x; i < NWIN; i += 1024) s_sc[i] = sc[i];
    __syncthreads();
    int w = part*1024 + threadIdx.x;
    float my = s_sc[w];
    int rank = 0;
    #pragma unroll 8
    for (int j = 0; j < NWIN; j++) {
        float v = s_sc[j];
        rank += (v > my) || (v == my && j < w);
    }
    if (rank < NWF) {
        int pos = atomicAdd(&g_cnt[b], 1);
        g_sel[b*NWF + pos] = w;
    }
}

// ---------------- 8x8 grid avg-pool (each cell = 64x64 block mean) ---------
__global__ void pool_kernel(const float* __restrict__ fm) {
    __shared__ float sp[512];
    int bci = blockIdx.x;          // (b*NC + c)*8 + ci
    int ci  = bci & 7;
    int bc  = bci >> 3;
    const float* base = fm + ((size_t)bc*NH + ci*64)*NW;
    int t = threadIdx.x;
    float acc = 0.f;
    #pragma unroll 4
    for (int r = 0; r < 64; r++) acc += base[(size_t)r*NW + t];
    sp[t] = acc;
    __syncthreads();
    for (int off = 32; off >= 1; off >>= 1) {
        if ((t & 63) < off) sp[t] += sp[t + off];
        __syncthreads();
    }
    if ((t & 63) == 0) {
        int cell = ci*8 + (t >> 6);
        g_gx[bc*64 + cell] = sp[t] * (1.0f/4096.0f);
    }
}

// ---------------- k,v = pooled @ kv_g_w^T -----------------------------------
__global__ void kv_kernel(const float* __restrict__ kvw) {
    __shared__ float sg[NC];
    int b = blockIdx.x >> 6;
    int p = blockIdx.x & 63;
    int c = threadIdx.x;
    sg[c] = g_gx[(b*NC + c)*64 + p];
    __syncthreads();
    float ka = 0.f, va = 0.f;
    #pragma unroll 8
    for (int cc = 0; cc < NC; cc++) {
        float g = sg[cc];
        ka = fmaf(g, kvw[c*NC + cc],        ka);
        va = fmaf(g, kvw[(c+NC)*NC + cc],   va);
    }
    g_kv[((size_t)b*64 + p)*NC + c]                    = ka;
    g_kv[(size_t)NB*64*NC + ((size_t)b*64 + p)*NC + c] = va;
}

// ---------------- fused per-window kernel -----------------------------------
// shared layout (floats): wf[64][129], x[64][129], y[64][129], attn[64][65]
#define SM_WF   0
#define SM_X    (64*129)
#define SM_Y    (2*64*129)
#define SM_ATTN (3*64*129)
#define SM_FLOATS (3*64*129 + 64*65)
#define SM_BYTES  (SM_FLOATS*4)

__device__ __forceinline__ float gelu_exact(float x) {
    return 0.5f * x * (1.0f + erff(x * 0.70710678118654752f));
}

// out[64][128] = in[64][128] @ W^T (+bias); W = tf32 bits, row-major [n][k]
// warp wp owns the n-strip [16*wp, 16*wp+16)
__device__ __forceinline__ void gemm128_mma(const float (*in)[129],
                                            const uint32_t* __restrict__ Wtf,
                                            const float* __restrict__ bias,
                                            float (*out)[129], int wp, int lane) {
    int g = lane >> 2, t = lane & 3;
    float c[4][2][4];
    #pragma unroll
    for (int mt = 0; mt < 4; mt++)
        #pragma unroll
        for (int nt = 0; nt < 2; nt++)
            #pragma unroll
            for (int k = 0; k < 4; k++) c[mt][nt][k] = 0.f;

    int n0 = wp * 16;
    #pragma unroll
    for (int k0 = 0; k0 < 128; k0 += 8) {
        uint32_t a[4][4];
        #pragma unroll
        for (int mt = 0; mt < 4; mt++) {
            const float* p0 = &in[mt*16 + g][k0 + t];
            const float* p1 = &in[mt*16 + g + 8][k0 + t];
            a[mt][0] = f2tf(p0[0]); a[mt][1] = f2tf(p1[0]);
            a[mt][2] = f2tf(p0[4]); a[mt][3] = f2tf(p1[4]);
        }
        uint32_t b[2][2];
        #pragma unroll
        for (int nt = 0; nt < 2; nt++) {
            int n = n0 + nt*8 + g;
            b[nt][0] = Wtf[n*128 + k0 + t];
            b[nt][1] = Wtf[n*128 + k0 + t + 4];
        }
        #pragma unroll
        for (int mt = 0; mt < 4; mt++)
            #pragma unroll
            for (int nt = 0; nt < 2; nt++)
                mma_tf32(c[mt][nt][0], c[mt][nt][1], c[mt][nt][2], c[mt][nt][3],
                         a[mt][0], a[mt][1], a[mt][2], a[mt][3], b[nt][0], b[nt][1]);
    }
    #pragma unroll
    for (int mt = 0; mt < 4; mt++)
        #pragma unroll
        for (int nt = 0; nt < 2; nt++) {
            int n = n0 + nt*8 + 2*t;
            float b0 = bias ? bias[n] : 0.f;
            float b1 = bias ? bias[n+1] : 0.f;
            out[mt*16 + g][n]       = c[mt][nt][0] + b0;
            out[mt*16 + g][n + 1]   = c[mt][nt][1] + b1;
            out[mt*16 + g + 8][n]     = c[mt][nt][2] + b0;
            out[mt*16 + g + 8][n + 1] = c[mt][nt][3] + b1;
        }
}

// attn[64][64] = SCALE * q[64][128] @ k[64][128]^T ; warp wp owns n-strip of 8
__device__ __forceinline__ void scores_qk_mma(const float (*q)[129], const float (*kk)[129],
                                              float (*attn)[65], int wp, int lane) {
    int g = lane >> 2, t = lane & 3;
    float c[4][4];
    #pragma unroll
    for (int mt = 0; mt < 4; mt++)
        #pragma unroll
        for (int k = 0; k < 4; k++) c[mt][k] = 0.f;

    int n0 = wp * 8;
    #pragma unroll
    for (int k0 = 0; k0 < 128; k0 += 8) {
        uint32_t a[4][4];
        #pragma unroll
        for (int mt = 0; mt < 4; mt++) {
            const float* p0 = &q[mt*16 + g][k0 + t];
            const float* p1 = &q[mt*16 + g + 8][k0 + t];
            a[mt][0] = f2tf(p0[0]); a[mt][1] = f2tf(p1[0]);
            a[mt][2] = f2tf(p0[4]); a[mt][3] = f2tf(p1[4]);
        }
        uint32_t b0 = f2tf(kk[n0 + g][k0 + t]);
        uint32_t b1 = f2tf(kk[n0 + g][k0 + t + 4]);
        #pragma unroll
        for (int mt = 0; mt < 4; mt++)
            mma_tf32(c[mt][0], c[mt][1], c[mt][2], c[mt][3],
                     a[mt][0], a[mt][1], a[mt][2], a[mt][3], b0, b1);
    }
    #pragma unroll
    for (int mt = 0; mt < 4; mt++) {
        int n = n0 + 2*t;
        attn[mt*16 + g][n]       = c[mt][0] * SCALE;
        attn[mt*16 + g][n + 1]   = c[mt][1] * SCALE;
        attn[mt*16 + g + 8][n]     = c[mt][2] * SCALE;
        attn[mt*16 + g + 8][n + 1] = c[mt][3] * SCALE;
    }
}

// out[64][128] = attn[64][64] @ v[64][128] ; warp wp owns n-strip of 16
__device__ __forceinline__ void gemm_av_mma(const float (*attn)[65], const float (*v)[129],
                                            float (*out)[129], int wp, int lane) {
    int g = lane >> 2, t = lane & 3;
    float c[4][2][4];
    #pragma unroll
    for (int mt = 0; mt < 4; mt++)
        #pragma unroll
        for (int nt = 0; nt < 2; nt++)
            #pragma unroll
            for (int k = 0; k < 4; k++) c[mt][nt][k] = 0.f;

    int n0 = wp * 16;
    #pragma unroll
    for (int k0 = 0; k0 < 64; k0 += 8) {
        uint32_t a[4][4];
        #pragma unroll
        for (int mt = 0; mt < 4; mt++) {
            a[mt][0] = f2tf(attn[mt*16 + g][k0 + t]);
            a[mt][1] = f2tf(attn[mt*16 + g + 8][k0 + t]);
            a[mt][2] = f2tf(attn[mt*16 + g][k0 + t + 4]);
            a[mt][3] = f2tf(attn[mt*16 + g + 8][k0 + t + 4]);
        }
        uint32_t b[2][2];
        #pragma unroll
        for (int nt = 0; nt < 2; nt++) {
            int n = n0 + nt*8 + g;
            b[nt][0] = f2tf(v[k0 + t][n]);
            b[nt][1] = f2tf(v[k0 + t + 4][n]);
        }
        #pragma unroll
        for (int mt = 0; mt < 4; mt++)
            #pragma unroll
            for (int nt = 0; nt < 2; nt++)
                mma_tf32(c[mt][nt][0], c[mt][nt][1], c[mt][nt][2], c[mt][nt][3],
                         a[mt][0], a[mt][1], a[mt][2], a[mt][3], b[nt][0], b[nt][1]);
    }
    #pragma unroll
    for (int mt = 0; mt < 4; mt++)
        #pragma unroll
        for (int nt = 0; nt < 2; nt++) {
            int n = n0 + nt*8 + 2*t;
            out[mt*16 + g][n]       = c[mt][nt][0];
            out[mt*16 + g][n + 1]   = c[mt][nt][1];
            out[mt*16 + g + 8][n]     = c[mt][nt][2];
            out[mt*16 + g + 8][n + 1] = c[mt][nt][3];
        }
}

// row-wise softmax over [64][64]; 4 threads per row (caller syncs before/after)
__device__ __forceinline__ void softmax64(float (*attn)[65], int tid) {
    int row = tid >> 2, q = tid & 3;
    float m = -1e30f;
    #pragma unroll
    for (int k = 0; k < 16; k++) m = fmaxf(m, attn[row][q*16 + k]);
    m = fmaxf(m, __shfl_xor_sync(0xffffffffu, m, 1));
    m = fmaxf(m, __shfl_xor_sync(0xffffffffu, m, 2));
    float s = 0.f;
    #pragma unroll
    for (int k = 0; k < 16; k++) {
        float e = expf(attn[row][q*16 + k] - m);
        attn[row][q*16 + k] = e;
        s += e;
    }
    s += __shfl_xor_sync(0xffffffffu, s, 1);
    s += __shfl_xor_sync(0xffffffffu, s, 2);
    float inv = 1.0f / s;
    #pragma unroll
    for (int k = 0; k < 16; k++) attn[row][q*16 + k] *= inv;
}

__global__ void __launch_bounds__(256, 1) window_kernel(
    const float* __restrict__ fm,
    const float* __restrict__ lb,
    const float* __restrict__ pb,
    float* __restrict__ out)
{
    extern __shared__ float sm[];
    float (*s_wf)[129]  = (float (*)[129])(sm + SM_WF);
    float (*s_x)[129]   = (float (*)[129])(sm + SM_X);
    float (*s_y)[129]   = (float (*)[129])(sm + SM_Y);
    float (*s_attn)[65] = (float (*)[65]) (sm + SM_ATTN);

    int tid = threadIdx.x, wp = tid >> 5, lane = tid & 31;
    int n = blockIdx.x;
    int b = n / NWF;
    int w = g_sel[n];
    int wh = w >> 6, ww = w & 63;
    const size_t plane = (size_t)NH * NW;
    const float* fbase = fm + (size_t)b*NC*plane + (size_t)(wh*8)*NW + ww*8;
    float*       obase = out + (size_t)b*NC*plane + (size_t)(wh*8)*NW + ww*8;

    // ---- gather window: s_wf[r*8+col][c] ----
    {
        int col = tid & 7, r = (tid >> 3) & 7, c0 = tid >> 6;
        #pragma unroll
        for (int k = 0; k < 32; k++) {
            int c = c0 + 4*k;
            s_wf[r*8 + col][c] = fbase[(size_t)c*plane + r*NW + col];
        }
    }
    __syncthreads();

    // ---- cross attention vs pooled k/v ----
    gemm128_mma(s_wf, g_wtf + WT_QG, nullptr, s_x, wp, lane);      // q -> s_x
    __syncthreads();
    {
        const float* kb = g_kv + (size_t)(b*64)*NC;
        #pragma unroll
        for (int k = 0; k < 32; k++) { int idx = tid + 256*k; s_y[idx >> 7][idx & 127] = kb[idx]; }
    }
    __syncthreads();
    scores_qk_mma(s_x, s_y, s_attn, wp, lane);
    __syncthreads();
    softmax64(s_attn, tid);
    __syncthreads();
    {
        const float* vb = g_kv + (size_t)NB*64*NC + (size_t)(b*64)*NC;
        #pragma unroll
        for (int k = 0; k < 32; k++) { int idx = tid + 256*k; s_y[idx >> 7][idx & 127] = vb[idx]; }
    }
    __syncthreads();
    gemm_av_mma(s_attn, s_y, s_x, wp, lane);
    __syncthreads();
    #pragma unroll
    for (int k = 0; k < 32; k++) {
        int idx = tid + 256*k;
        s_wf[idx >> 7][idx & 127] += s_x[idx >> 7][idx & 127];
    }
    __syncthreads();

    // ---- MLP 1: wf += gelu(wf @ linner0^T + b) ----
    gemm128_mma(s_wf, g_wtf + WT_LIN, lb, s_x, wp, lane);
    __syncthreads();
    #pragma unroll
    for (int k = 0; k < 32; k++) {
        int idx = tid + 256*k;
        s_wf[idx >> 7][idx & 127] += gelu_exact(s_x[idx >> 7][idx & 127]);
    }
    __syncthreads();

    // ---- window self-attention ----
    gemm128_mma(s_wf, g_wtf + WT_Q2, nullptr, s_x, wp, lane);      // q2 -> s_x
    gemm128_mma(s_wf, g_wtf + WT_K2, nullptr, s_y, wp, lane);      // k2 -> s_y
    __syncthreads();
    scores_qk_mma(s_x, s_y, s_attn, wp, lane);
    __syncthreads();
    softmax64(s_attn, tid);
    gemm128_mma(s_wf, g_wtf + WT_V2, nullptr, s_x, wp, lane);      // v2 -> s_x (q2 dead)
    __syncthreads();
    gemm_av_mma(s_attn, s_x, s_y, wp, lane);                       // av -> s_y (k2 dead)
    __syncthreads();
    // scrambled residual from reference's swapaxes+reshape:
    // wf[i][j] += av[j%64][2*i + j/64]
    #pragma unroll
    for (int k = 0; k < 32; k++) {
        int idx = tid + 256*k;
        int i = idx >> 7, j = idx & 127;
        s_wf[i][j] += s_y[j & 63][2*i + (j >> 6)];
    }
    __syncthreads();

    // ---- MLP 2: wf += gelu(wf @ proj^T + b) ----
    gemm128_mma(s_wf, g_wtf + WT_PROJ, pb, s_x, wp, lane);
    __syncthreads();
    #pragma unroll
    for (int k = 0; k < 32; k++) {
        int idx = tid + 256*k;
        s_wf[idx >> 7][idx & 127] += gelu_exact(s_x[idx >> 7][idx & 127]);
    }
    __syncthreads();

    // ---- scatter back ----
    {
        int col = tid & 7, r = (tid >> 3) & 7, c0 = tid >> 6;
        #pragma unroll
        for (int k = 0; k < 32; k++) {
            int c = c0 + 4*k;
            obase[(size_t)c*plane + r*NW + col] = s_wf[r*8 + col][c];
        }
    }
}

// ---------------- launch -----------------------------------------------------
extern "C" void kernel_launch(void* const* d_in, const int* in_sizes, int n_in,
                              void* d_out, int out_size) {
    const float* fm   = (const float*)d_in[0];
    const float* unc  = (const float*)d_in[1];
    const float* qgw  = (const float*)d_in[2];
    const float* kvw  = (const float*)d_in[3];
    const float* lw   = (const float*)d_in[4];
    const float* lb   = (const float*)d_in[5];
    const float* qkvw = (const float*)d_in[6];
    const float* pw   = (const float*)d_in[7];
    const float* pb   = (const float*)d_in[8];
    float* out = (float*)d_out;

    cudaFuncSetAttribute(window_kernel,
                         cudaFuncAttributeMaxDynamicSharedMemorySize, SM_BYTES);

    // output starts as a copy of the input feature map
    cudaMemcpyAsync(out, fm, sizeof(float)*(size_t)NB*NC*NH*NW,
                    cudaMemcpyDeviceToDevice, 0);

    wprep_kernel<<<384, 256>>>(qgw, lw, qkvw, pw);
    scores_kernel<<<1024, 256>>>(unc);
    select_kernel<<<8, 1024>>>();
    pool_kernel<<<NB*NC*8, 512>>>(fm);
    kv_kernel<<<NB*64, 128>>>(kvw);
    window_kernel<<<NSEL, 256, SM_BYTES>>>(fm, lb, pb, out);
}

// round 5
// speedup vs baseline: 1.4745x; 1.4745x over previous
#include <cuda_runtime.h>
#include <math.h>
#include <stdint.h>

#define NB    2
#define NC    128
#define NH    512
#define NW    512
#define NWIN  4096      // 64 x 64 windows
#define NWF   1228      // int(4096 * 0.3)
#define NSEL  (NB*NWF)  // 2456
#define WINSZ 64
#define SCALE 0.08838834764831845f   // 128^-0.5

// ---------------- scratch (static device globals; allocation-free) ----------
__device__ float    g_score[NB*NWIN];
__device__ int      g_sel[NB*NWF];
__device__ int      g_cnt[NB];
__device__ float    g_gx[NB*NC*64];          // pooled features [b][c][cell]
__device__ float    g_kv[2*NB*64*NC];        // k then v: [b][p][c]
__device__ uint32_t g_wtf[6*128*128];        // tf32-rounded weights
// offsets into g_wtf (in 128x128 matrices): 0=qgw, 1=linner0, 2=q2, 3=k2, 4=v2, 5=proj
#define WT_QG   (0*16384)
#define WT_LIN  (1*16384)
#define WT_Q2   (2*16384)
#define WT_K2   (3*16384)
#define WT_V2   (4*16384)
#define WT_PROJ (5*16384)

// ---------------- tf32 helpers ----------------------------------------------
__device__ __forceinline__ uint32_t f2tf(float f) {
    uint32_t r;
    asm("cvt.rna.tf32.f32 %0, %1;" : "=r"(r) : "f"(f));
    return r;
}

__device__ __forceinline__ void mma_tf32(float& c0, float& c1, float& c2, float& c3,
                                         uint32_t a0, uint32_t a1, uint32_t a2, uint32_t a3,
                                         uint32_t b0, uint32_t b1) {
    asm volatile("mma.sync.aligned.m16n8k8.row.col.f32.tf32.tf32.f32 "
                 "{%0,%1,%2,%3}, {%4,%5,%6,%7}, {%8,%9}, {%0,%1,%2,%3};"
                 : "+f"(c0), "+f"(c1), "+f"(c2), "+f"(c3)
                 : "r"(a0), "r"(a1), "r"(a2), "r"(a3), "r"(b0), "r"(b1));
}

// ---------------- weight prep: fp32 -> tf32 bits ----------------------------
__global__ void wprep_kernel(const float* __restrict__ qgw, const float* __restrict__ lw,
                             const float* __restrict__ qkvw, const float* __restrict__ pw) {
    int i = blockIdx.x * 256 + threadIdx.x;           // 98304 total
    float v;
    if      (i < 16384) v = qgw[i];
    else if (i < 32768) v = lw[i - 16384];
    else if (i < 81920) v = qkvw[i - 32768];
    else                v = pw[i - 81920];
    g_wtf[i] = f2tf(v);
}

// ---------------- window scores (double accumulation, rounded to fp32) -----
__global__ void scores_kernel(const float* __restrict__ unc) {
    if (blockIdx.x == 0 && threadIdx.x < NB) g_cnt[threadIdx.x] = 0;
    int gw   = blockIdx.x * 8 + (threadIdx.x >> 5);
    int lane = threadIdx.x & 31;
    if (gw >= NB*NWIN) return;
    int b = gw / NWIN, w = gw % NWIN;
    int wh = w >> 6, ww = w & 63;
    const float* base = unc + ((size_t)b*NH + wh*8)*NW + ww*8;
    int r0 = lane >> 3, c0 = lane & 7;
    double s = (double)base[r0*NW + c0] + (double)base[(r0+4)*NW + c0];
    #pragma unroll
    for (int o = 16; o; o >>= 1) s += __shfl_down_sync(0xffffffffu, s, o);
    if (lane == 0) g_score[gw] = (float)(s * (1.0/64.0));
}

// ---------------- stable top-k via rank (score desc, index asc) ------------
__global__ void select_kernel() {
    __shared__ float s_sc[NWIN];
    int b = blockIdx.x >> 2;
    int part = blockIdx.x & 3;
    const float* sc = g_score + b*NWIN;
    for (int i = threadIdx.x; i < NWIN; i += 1024) s_sc[i] = sc[i];
    __syncthreads();
    int w = part*1024 + threadIdx.x;
    float my = s_sc[w];
    int rank = 0;
    #pragma unroll 8
    for (int j = 0; j < NWIN; j++) {
        float v = s_sc[j];
        rank += (v > my) || (v == my && j < w);
    }
    if (rank < NWF) {
        int pos = atomicAdd(&g_cnt[b], 1);
        g_sel[b*NWF + pos] = w;
    }
}

// ---------------- 8x8 grid avg-pool (each cell = 64x64 block mean) ---------
__global__ void pool_kernel(const float* __restrict__ fm) {
    __shared__ float sp[512];
    int bci = blockIdx.x;          // (b*NC + c)*8 + ci
    int ci  = bci & 7;
    int bc  = bci >> 3;
    const float* base = fm + ((size_t)bc*NH + ci*64)*NW;
    int t = threadIdx.x;
    float acc = 0.f;
    #pragma unroll 4
    for (int r = 0; r < 64; r++) acc += base[(size_t)r*NW + t];
    sp[t] = acc;
    __syncthreads();
    for (int off = 32; off >= 1; off >>= 1) {
        if ((t & 63) < off) sp[t] += sp[t + off];
        __syncthreads();
    }
    if ((t & 63) == 0) {
        int cell = ci*8 + (t >> 6);
        g_gx[bc*64 + cell] = sp[t] * (1.0f/4096.0f);
    }
}

// ---------------- k,v = pooled @ kv_g_w^T -----------------------------------
__global__ void kv_kernel(const float* __restrict__ kvw) {
    __shared__ float sg[NC];
    int b = blockIdx.x >> 6;
    int p = blockIdx.x & 63;
    int c = threadIdx.x;
    sg[c] = g_gx[(b*NC + c)*64 + p];
    __syncthreads();
    float ka = 0.f, va = 0.f;
    #pragma unroll 8
    for (int cc = 0; cc < NC; cc++) {
        float g = sg[cc];
        ka = fmaf(g, kvw[c*NC + cc],        ka);
        va = fmaf(g, kvw[(c+NC)*NC + cc],   va);
    }
    g_kv[((size_t)b*64 + p)*NC + c]                    = ka;
    g_kv[(size_t)NB*64*NC + ((size_t)b*64 + p)*NC + c] = va;
}

// ---------------- fused per-window kernel -----------------------------------
// shared layout (floats): wf[64][129], x[64][129], y[64][129], attn[64][65]
#define SM_WF   0
#define SM_X    (64*129)
#define SM_Y    (2*64*129)
#define SM_ATTN (3*64*129)
#define SM_FLOATS (3*64*129 + 64*65)
#define SM_BYTES  (SM_FLOATS*4)

__device__ __forceinline__ float gelu_exact(float x) {
    return 0.5f * x * (1.0f + erff(x * 0.70710678118654752f));
}

// out[64][128] = in[64][128] @ W^T (+bias); W = tf32 bits, row-major [n][k]
// warp wp owns the n-strip [16*wp, 16*wp+16)
__device__ __forceinline__ void gemm128_mma(const float (*in)[129],
                                            const uint32_t* __restrict__ Wtf,
                                            const float* __restrict__ bias,
                                            float (*out)[129], int wp, int lane) {
    int g = lane >> 2, t = lane & 3;
    float c[4][2][4];
    #pragma unroll
    for (int mt = 0; mt < 4; mt++)
        #pragma unroll
        for (int nt = 0; nt < 2; nt++)
            #pragma unroll
            for (int k = 0; k < 4; k++) c[mt][nt][k] = 0.f;

    int n0 = wp * 16;
    #pragma unroll
    for (int k0 = 0; k0 < 128; k0 += 8) {
        uint32_t a[4][4];
        #pragma unroll
        for (int mt = 0; mt < 4; mt++) {
            const float* p0 = &in[mt*16 + g][k0 + t];
            const float* p1 = &in[mt*16 + g + 8][k0 + t];
            a[mt][0] = f2tf(p0[0]); a[mt][1] = f2tf(p1[0]);
            a[mt][2] = f2tf(p0[4]); a[mt][3] = f2tf(p1[4]);
        }
        uint32_t b[2][2];
        #pragma unroll
        for (int nt = 0; nt < 2; nt++) {
            int n = n0 + nt*8 + g;
            b[nt][0] = Wtf[n*128 + k0 + t];
            b[nt][1] = Wtf[n*128 + k0 + t + 4];
        }
        #pragma unroll
        for (int mt = 0; mt < 4; mt++)
            #pragma unroll
            for (int nt = 0; nt < 2; nt++)
                mma_tf32(c[mt][nt][0], c[mt][nt][1], c[mt][nt][2], c[mt][nt][3],
                         a[mt][0], a[mt][1], a[mt][2], a[mt][3], b[nt][0], b[nt][1]);
    }
    #pragma unroll
    for (int mt = 0; mt < 4; mt++)
        #pragma unroll
        for (int nt = 0; nt < 2; nt++) {
            int n = n0 + nt*8 + 2*t;
            float b0 = bias ? bias[n] : 0.f;
            float b1 = bias ? bias[n+1] : 0.f;
            out[mt*16 + g][n]       = c[mt][nt][0] + b0;
            out[mt*16 + g][n + 1]   = c[mt][nt][1] + b1;
            out[mt*16 + g + 8][n]     = c[mt][nt][2] + b0;
            out[mt*16 + g + 8][n + 1] = c[mt][nt][3] + b1;
        }
}

// attn[64][64] = SCALE * q[64][128] @ k[64][128]^T ; warp wp owns n-strip of 8
__device__ __forceinline__ void scores_qk_mma(const float (*q)[129], const float (*kk)[129],
                                              float (*attn)[65], int wp, int lane) {
    int g = lane >> 2, t = lane & 3;
    float c[4][4];
    #pragma unroll
    for (int mt = 0; mt < 4; mt++)
        #pragma unroll
        for (int k = 0; k < 4; k++) c[mt][k] = 0.f;

    int n0 = wp * 8;
    #pragma unroll
    for (int k0 = 0; k0 < 128; k0 += 8) {
        uint32_t a[4][4];
        #pragma unroll
        for (int mt = 0; mt < 4; mt++) {
            const float* p0 = &q[mt*16 + g][k0 + t];
            const float* p1 = &q[mt*16 + g + 8][k0 + t];
            a[mt][0] = f2tf(p0[0]); a[mt][1] = f2tf(p1[0]);
            a[mt][2] = f2tf(p0[4]); a[mt][3] = f2tf(p1[4]);
        }
        uint32_t b0 = f2tf(kk[n0 + g][k0 + t]);
        uint32_t b1 = f2tf(kk[n0 + g][k0 + t + 4]);
        #pragma unroll
        for (int mt = 0; mt < 4; mt++)
            mma_tf32(c[mt][0], c[mt][1], c[mt][2], c[mt][3],
                     a[mt][0], a[mt][1], a[mt][2], a[mt][3], b0, b1);
    }
    #pragma unroll
    for (int mt = 0; mt < 4; mt++) {
        int n = n0 + 2*t;
        attn[mt*16 + g][n]       = c[mt][0] * SCALE;
        attn[mt*16 + g][n + 1]   = c[mt][1] * SCALE;
        attn[mt*16 + g + 8][n]     = c[mt][2] * SCALE;
        attn[mt*16 + g + 8][n + 1] = c[mt][3] * SCALE;
    }
}

// out[64][128] = attn[64][64] @ v[64][128] ; warp wp owns n-strip of 16
__device__ __forceinline__ void gemm_av_mma(const float (*attn)[65], const float (*v)[129],
                                            float (*out)[129], int wp, int lane) {
    int g = lane >> 2, t = lane & 3;
    float c[4][2][4];
    #pragma unroll
    for (int mt = 0; mt < 4; mt++)
        #pragma unroll
        for (int nt = 0; nt < 2; nt++)
            #pragma unroll
            for (int k = 0; k < 4; k++) c[mt][nt][k] = 0.f;

    int n0 = wp * 16;
    #pragma unroll
    for (int k0 = 0; k0 < 64; k0 += 8) {
        uint32_t a[4][4];
        #pragma unroll
        for (int mt = 0; mt < 4; mt++) {
            a[mt][0] = f2tf(attn[mt*16 + g][k0 + t]);
            a[mt][1] = f2tf(attn[mt*16 + g + 8][k0 + t]);
            a[mt][2] = f2tf(attn[mt*16 + g][k0 + t + 4]);
            a[mt][3] = f2tf(attn[mt*16 + g + 8][k0 + t + 4]);
        }
        uint32_t b[2][2];
        #pragma unroll
        for (int nt = 0; nt < 2; nt++) {
            int n = n0 + nt*8 + g;
            b[nt][0] = f2tf(v[k0 + t][n]);
            b[nt][1] = f2tf(v[k0 + t + 4][n]);
        }
        #pragma unroll
        for (int mt = 0; mt < 4; mt++)
            #pragma unroll
            for (int nt = 0; nt < 2; nt++)
                mma_tf32(c[mt][nt][0], c[mt][nt][1], c[mt][nt][2], c[mt][nt][3],
                         a[mt][0], a[mt][1], a[mt][2], a[mt][3], b[nt][0], b[nt][1]);
    }
    #pragma unroll
    for (int mt = 0; mt < 4; mt++)
        #pragma unroll
        for (int nt = 0; nt < 2; nt++) {
            int n = n0 + nt*8 + 2*t;
            out[mt*16 + g][n]       = c[mt][nt][0];
            out[mt*16 + g][n + 1]   = c[mt][nt][1];
            out[mt*16 + g + 8][n]     = c[mt][nt][2];
            out[mt*16 + g + 8][n + 1] = c[mt][nt][3];
        }
}

// row-wise softmax over [64][64]; 4 threads per row (caller syncs before/after)
__device__ __forceinline__ void softmax64(float (*attn)[65], int tid) {
    int row = tid >> 2, q = tid & 3;
    float m = -1e30f;
    #pragma unroll
    for (int k = 0; k < 16; k++) m = fmaxf(m, attn[row][q*16 + k]);
    m = fmaxf(m, __shfl_xor_sync(0xffffffffu, m, 1));
    m = fmaxf(m, __shfl_xor_sync(0xffffffffu, m, 2));
    float s = 0.f;
    #pragma unroll
    for (int k = 0; k < 16; k++) {
        float e = expf(attn[row][q*16 + k] - m);
        attn[row][q*16 + k] = e;
        s += e;
    }
    s += __shfl_xor_sync(0xffffffffu, s, 1);
    s += __shfl_xor_sync(0xffffffffu, s, 2);
    float inv = 1.0f / s;
    #pragma unroll
    for (int k = 0; k < 16; k++) attn[row][q*16 + k] *= inv;
}

__global__ void __launch_bounds__(256, 1) window_kernel(
    const float* __restrict__ fm,
    const float* __restrict__ lb,
    const float* __restrict__ pb,
    float* __restrict__ out)
{
    extern __shared__ float sm[];
    float (*s_wf)[129]  = (float (*)[129])(sm + SM_WF);
    float (*s_x)[129]   = (float (*)[129])(sm + SM_X);
    float (*s_y)[129]   = (float (*)[129])(sm + SM_Y);
    float (*s_attn)[65] = (float (*)[65]) (sm + SM_ATTN);

    int tid = threadIdx.x, wp = tid >> 5, lane = tid & 31;
    int n = blockIdx.x;
    int b = n / NWF;
    int w = g_sel[n];
    int wh = w >> 6, ww = w & 63;
    const size_t plane = (size_t)NH * NW;
    const float* fbase = fm + (size_t)b*NC*plane + (size_t)(wh*8)*NW + ww*8;
    float*       obase = out + (size_t)b*NC*plane + (size_t)(wh*8)*NW + ww*8;

    // ---- gather window: s_wf[r*8+col][c] ----
    {
        int col = tid & 7, r = (tid >> 3) & 7, c0 = tid >> 6;
        #pragma unroll
        for (int k = 0; k < 32; k++) {
            int c = c0 + 4*k;
            s_wf[r*8 + col][c] = fbase[(size_t)c*plane + r*NW + col];
        }
    }
    __syncthreads();

    // ---- cross attention vs pooled k/v ----
    gemm128_mma(s_wf, g_wtf + WT_QG, nullptr, s_x, wp, lane);      // q -> s_x
    __syncthreads();
    {
        const float* kb = g_kv + (size_t)(b*64)*NC;
        #pragma unroll
        for (int k = 0; k < 32; k++) { int idx = tid + 256*k; s_y[idx >> 7][idx & 127] = kb[idx]; }
    }
    __syncthreads();
    scores_qk_mma(s_x, s_y, s_attn, wp, lane);
    __syncthreads();
    softmax64(s_attn, tid);
    __syncthreads();
    {
        const float* vb = g_kv + (size_t)NB*64*NC + (size_t)(b*64)*NC;
        #pragma unroll
        for (int k = 0; k < 32; k++) { int idx = tid + 256*k; s_y[idx >> 7][idx & 127] = vb[idx]; }
    }
    __syncthreads();
    gemm_av_mma(s_attn, s_y, s_x, wp, lane);
    __syncthreads();
    #pragma unroll
    for (int k = 0; k < 32; k++) {
        int idx = tid + 256*k;
        s_wf[idx >> 7][idx & 127] += s_x[idx >> 7][idx & 127];
    }
    __syncthreads();

    // ---- MLP 1: wf += gelu(wf @ linner0^T + b) ----
    gemm128_mma(s_wf, g_wtf + WT_LIN, lb, s_x, wp, lane);
    __syncthreads();
    #pragma unroll
    for (int k = 0; k < 32; k++) {
        int idx = tid + 256*k;
        s_wf[idx >> 7][idx & 127] += gelu_exact(s_x[idx >> 7][idx & 127]);
    }
    __syncthreads();

    // ---- window self-attention ----
    gemm128_mma(s_wf, g_wtf + WT_Q2, nullptr, s_x, wp, lane);      // q2 -> s_x
    gemm128_mma(s_wf, g_wtf + WT_K2, nullptr, s_y, wp, lane);      // k2 -> s_y
    __syncthreads();
    scores_qk_mma(s_x, s_y, s_attn, wp, lane);
    __syncthreads();
    softmax64(s_attn, tid);
    gemm128_mma(s_wf, g_wtf + WT_V2, nullptr, s_x, wp, lane);      // v2 -> s_x (q2 dead)
    __syncthreads();
    gemm_av_mma(s_attn, s_x, s_y, wp, lane);                       // av -> s_y (k2 dead)
    __syncthreads();
    // scrambled residual from reference's swapaxes+reshape:
    // wf[i][j] += av[j%64][2*i + j/64]
    #pragma unroll
    for (int k = 0; k < 32; k++) {
        int idx = tid + 256*k;
        int i = idx >> 7, j = idx & 127;
        s_wf[i][j] += s_y[j & 63][2*i + (j >> 6)];
    }
    __syncthreads();

    // ---- MLP 2: wf += gelu(wf @ proj^T + b) ----
    gemm128_mma(s_wf, g_wtf + WT_PROJ, pb, s_x, wp, lane);
    __syncthreads();
    #pragma unroll
    for (int k = 0; k < 32; k++) {
        int idx = tid + 256*k;
        s_wf[idx >> 7][idx & 127] += gelu_exact(s_x[idx >> 7][idx & 127]);
    }
    __syncthreads();

    // ---- scatter back ----
    {
        int col = tid & 7, r = (tid >> 3) & 7, c0 = tid >> 6;
        #pragma unroll
        for (int k = 0; k < 32; k++) {
            int c = c0 + 4*k;
            obase[(size_t)c*plane + r*NW + col] = s_wf[r*8 + col][c];
        }
    }
}

// ---------------- launch -----------------------------------------------------
extern "C" void kernel_launch(void* const* d_in, const int* in_sizes, int n_in,
                              void* d_out, int out_size) {
    const float* fm   = (const float*)d_in[0];
    const float* unc  = (const float*)d_in[1];
    const float* qgw  = (const float*)d_in[2];
    const float* kvw  = (const float*)d_in[3];
    const float* lw   = (const float*)d_in[4];
    const float* lb   = (const float*)d_in[5];
    const float* qkvw = (const float*)d_in[6];
    const float* pw   = (const float*)d_in[7];
    const float* pb   = (const float*)d_in[8];
    float* out = (float*)d_out;

    cudaFuncSetAttribute(window_kernel,
                         cudaFuncAttributeMaxDynamicSharedMemorySize, SM_BYTES);

    // output starts as a copy of the input feature map
    cudaMemcpyAsync(out, fm, sizeof(float)*(size_t)NB*NC*NH*NW,
                    cudaMemcpyDeviceToDevice, 0);

    wprep_kernel<<<384, 256>>>(qgw, lw, qkvw, pw);
    scores_kernel<<<1024, 256>>>(unc);
    select_kernel<<<8, 1024>>>();
    pool_kernel<<<NB*NC*8, 512>>>(fm);
    kv_kernel<<<NB*64, 128>>>(kvw);
    window_kernel<<<NSEL, 256, SM_BYTES>>>(fm, lb, pb, out);
}

// round 6
// speedup vs baseline: 4.2786x; 2.9016x over previous
#include <cuda_runtime.h>
#include <cuda_fp16.h>
#include <math.h>
#include <stdint.h>

#define NB    2
#define NC    128
#define NH    512
#define NW    512
#define NWIN  4096
#define NWF   1228
#define NSEL  (NB*NWF)
#define SCALE 0.08838834764831845f

// ---------------- static device scratch -------------------------------------
__device__ float g_score[NB*NWIN];
__device__ int   g_sel[NB*NWF];
__device__ int   g_cnt[NB];
__device__ float g_gx[NB*NC*64];
__device__ __align__(16) uint2  g_wfrag[6*4096];        // fragment-major weights
__device__ __align__(16) __half g_k16[NB*64*128];       // cross-attn K row-major
__device__ __align__(16) __half g_v1t[NB*128*64];       // cross-attn V transposed

#define MAT_QG 0
#define MAT_LIN 1
#define MAT_Q2 2
#define MAT_K2 3
#define MAT_V2 4
#define MAT_PR 5

// ---------------- helpers ----------------------------------------------------
__device__ __forceinline__ uint32_t h2u(float a, float b) {
    __half2 h = __floats2half2_rn(a, b);
    return reinterpret_cast<uint32_t&>(h);
}
__device__ __forceinline__ void mma16(float* c, uint32_t a0, uint32_t a1,
                                      uint32_t a2, uint32_t a3,
                                      uint32_t b0, uint32_t b1) {
    asm volatile("mma.sync.aligned.m16n8k16.row.col.f32.f16.f16.f32 "
                 "{%0,%1,%2,%3}, {%4,%5,%6,%7}, {%8,%9}, {%0,%1,%2,%3};"
                 : "+f"(c[0]), "+f"(c[1]), "+f"(c[2]), "+f"(c[3])
                 : "r"(a0), "r"(a1), "r"(a2), "r"(a3), "r"(b0), "r"(b1));
}
__device__ __forceinline__ float gelu_exact(float x) {
    return 0.5f * x * (1.0f + erff(x * 0.70710678118654752f));
}

// ---------------- prep kernels ----------------------------------------------
// weights -> fragment-major fp16: idx = mat*4096 + (kb*16+n8)*32 + lane
__global__ void wprep_kernel(const float* __restrict__ qgw, const float* __restrict__ lw,
                             const float* __restrict__ qkvw, const float* __restrict__ pw) {
    int i = blockIdx.x * 256 + threadIdx.x;          // 24576
    int mat = i >> 12, r = i & 4095;
    int kb = r >> 9, n8 = (r >> 5) & 15, lane = r & 31;
    int g = lane >> 2, t = lane & 3;
    int n = n8*8 + g, k = kb*16 + 2*t;
    const float* W = (mat == 0) ? qgw : (mat == 1) ? lw
                   : (mat <= 4) ? qkvw + (mat - 2)*16384 : pw;
    const float* row = W + n*128;
    uint2 o;
    o.x = h2u(row[k],   row[k+1]);
    o.y = h2u(row[k+8], row[k+9]);
    g_wfrag[i] = o;
}

__global__ void scores_kernel(const float* __restrict__ unc) {
    if (blockIdx.x == 0 && threadIdx.x < NB) g_cnt[threadIdx.x] = 0;
    int gw = blockIdx.x * 8 + (threadIdx.x >> 5);
    int lane = threadIdx.x & 31;
    if (gw >= NB*NWIN) return;
    int b = gw / NWIN, w = gw % NWIN;
    int wh = w >> 6, ww = w & 63;
    const float* base = unc + ((size_t)b*NH + wh*8)*NW + ww*8;
    int r0 = lane >> 3, c0 = lane & 7;
    double s = (double)base[r0*NW + c0] + (double)base[(r0+4)*NW + c0];
    #pragma unroll
    for (int o = 16; o; o >>= 1) s += __shfl_down_sync(0xffffffffu, s, o);
    if (lane == 0) g_score[gw] = (float)(s * (1.0/64.0));
}

__global__ void select_kernel() {
    __shared__ float s_sc[NWIN];
    int b = blockIdx.x >> 2, part = blockIdx.x & 3;
    const float* sc = g_score + b*NWIN;
    for (int i = threadIdx.x; i < NWIN; i += 1024) s_sc[i] = sc[i];
    __syncthreads();
    int w = part*1024 + threadIdx.x;
    float my = s_sc[w];
    int rank = 0;
    #pragma unroll 8
    for (int j = 0; j < NWIN; j++) {
        float v = s_sc[j];
        rank += (v > my) || (v == my && j < w);
    }
    if (rank < NWF) {
        int pos = atomicAdd(&g_cnt[b], 1);
        g_sel[b*NWF + pos] = w;
    }
}

// fused copy + 8x8 grid average pool (reads fm once)
__global__ void copy_pool_kernel(const float* __restrict__ fm, float* __restrict__ out) {
    __shared__ float sp[512];
    int bci = blockIdx.x, ci = bci & 7, bc = bci >> 3;
    const float* base = fm  + ((size_t)bc*NH + ci*64)*NW;
    float*       ob   = out + ((size_t)bc*NH + ci*64)*NW;
    int t = threadIdx.x;
    float acc = 0.f;
    #pragma unroll 4
    for (int r = 0; r < 64; r++) {
        float v = base[(size_t)r*NW + t];
        ob[(size_t)r*NW + t] = v;
        acc += v;
    }
    sp[t] = acc;
    __syncthreads();
    for (int off = 32; off >= 1; off >>= 1) {
        if ((t & 63) < off) sp[t] += sp[t + off];
        __syncthreads();
    }
    if ((t & 63) == 0) g_gx[bc*64 + ci*8 + (t >> 6)] = sp[t] * (1.0f/4096.0f);
}

// k1, v1 for cross attention -> fp16 (K row-major, V transposed)
__global__ void kv_kernel(const float* __restrict__ kvw) {
    __shared__ float sg[NC];
    int b = blockIdx.x >> 6, p = blockIdx.x & 63;
    int tid = threadIdx.x;
    int c = tid & 127;
    bool isv = tid >= 128;
    if (tid < 128) sg[tid] = g_gx[(b*NC + tid)*64 + p];
    __syncthreads();
    const float* wr = kvw + (size_t)(c + (isv ? NC : 0)) * NC;
    float a = 0.f;
    #pragma unroll 8
    for (int cc = 0; cc < NC; cc++) a = fmaf(sg[cc], wr[cc], a);
    if (!isv) g_k16[(b*64 + p)*128 + c] = __float2half(a);
    else      g_v1t[(b*128 + c)*64 + p] = __float2half(a);
}

// ---------------- fused window kernel ----------------------------------------
#define AST 136    // half stride (s_a, s_b)
#define VST 72     // half stride (s_vt)
#define WST 132    // float stride (s_wf)
#define PST 68     // float stride (s_p)
// byte offsets (all 16B aligned)
#define OFF_WF 0
#define OFF_P  33792
#define OFF_A  51200
#define OFF_B  68608
#define OFF_VT 86016
#define SMEMB  104448

__device__ __forceinline__ uint32_t ldh2(const __half* p) {
    return *reinterpret_cast<const uint32_t*>(p);
}

// C[4][2][4] = A(s_a 64x128) @ W^T via fragment-major weights
__device__ __forceinline__ void gemmW(const __half* sa, const uint2* wf,
                                      int lane, int wp, float C[4][2][4]) {
    int g = lane >> 2, t = lane & 3;
    #pragma unroll
    for (int mt = 0; mt < 4; mt++)
        #pragma unroll
        for (int nt = 0; nt < 2; nt++)
            #pragma unroll
            for (int k = 0; k < 4; k++) C[mt][nt][k] = 0.f;
    #pragma unroll
    for (int kb = 0; kb < 8; kb++) {
        uint2 w0 = __ldg(&wf[(kb*16 + 2*wp    )*32 + lane]);
        uint2 w1 = __ldg(&wf[(kb*16 + 2*wp + 1)*32 + lane]);
        int kc = kb*16 + 2*t;
        #pragma unroll
        for (int mt = 0; mt < 4; mt++) {
            const __half* p0 = sa + (mt*16 + g)*AST + kc;
            uint32_t a0 = ldh2(p0), a1 = ldh2(p0 + 8*AST);
            uint32_t a2 = ldh2(p0 + 8), a3 = ldh2(p0 + 8*AST + 8);
            mma16(C[mt][0], a0, a1, a2, a3, w0.x, w0.y);
            mma16(C[mt][1], a0, a1, a2, a3, w1.x, w1.y);
        }
    }
}

// C[4][4] = Q(s_a) @ K(s_b)^T, N=64 (strip of 8 per warp)
__device__ __forceinline__ void gemmQK(const __half* sa, const __half* sb,
                                       int lane, int wp, float C[4][4]) {
    int g = lane >> 2, t = lane & 3;
    #pragma unroll
    for (int mt = 0; mt < 4; mt++)
        #pragma unroll
        for (int k = 0; k < 4; k++) C[mt][k] = 0.f;
    #pragma unroll
    for (int kb = 0; kb < 8; kb++) {
        const __half* kp = sb + (wp*8 + g)*AST + kb*16 + 2*t;
        uint32_t b0 = ldh2(kp), b1 = ldh2(kp + 8);
        int kc = kb*16 + 2*t;
        #pragma unroll
        for (int mt = 0; mt < 4; mt++) {
            const __half* p0 = sa + (mt*16 + g)*AST + kc;
            uint32_t a0 = ldh2(p0), a1 = ldh2(p0 + 8*AST);
            uint32_t a2 = ldh2(p0 + 8), a3 = ldh2(p0 + 8*AST + 8);
            mma16(C[mt], a0, a1, a2, a3, b0, b1);
        }
    }
}

// C[4][2][4] = attn(s_a cols 0..63) @ V (s_vt transposed), K=64
__device__ __forceinline__ void gemmAV(const __half* sa, const __half* svt,
                                       int lane, int wp, float C[4][2][4]) {
    int g = lane >> 2, t = lane & 3;
    #pragma unroll
    for (int mt = 0; mt < 4; mt++)
        #pragma unroll
        for (int nt = 0; nt < 2; nt++)
            #pragma unroll
            for (int k = 0; k < 4; k++) C[mt][nt][k] = 0.f;
    #pragma unroll
    for (int kb = 0; kb < 4; kb++) {
        int kc = kb*16 + 2*t;
        uint32_t b[2][2];
        #pragma unroll
        for (int nt = 0; nt < 2; nt++) {
            const __half* vp = svt + (wp*16 + nt*8 + g)*VST + kc;
            b[nt][0] = ldh2(vp); b[nt][1] = ldh2(vp + 8);
        }
        #pragma unroll
        for (int mt = 0; mt < 4; mt++) {
            const __half* p0 = sa + (mt*16 + g)*AST + kc;
            uint32_t a0 = ldh2(p0), a1 = ldh2(p0 + 8*AST);
            uint32_t a2 = ldh2(p0 + 8), a3 = ldh2(p0 + 8*AST + 8);
            mma16(C[mt][0], a0, a1, a2, a3, b[0][0], b[0][1]);
            mma16(C[mt][1], a0, a1, a2, a3, b[1][0], b[1][1]);
        }
    }
}

__global__ void __launch_bounds__(256) window_kernel(
    const float* __restrict__ fm,
    const float* __restrict__ lb, const float* __restrict__ pb,
    float* __restrict__ out)
{
    extern __shared__ char sm[];
    float*  s_wf = (float*) (sm + OFF_WF);
    float*  s_p  = (float*) (sm + OFF_P);
    __half* s_a  = (__half*)(sm + OFF_A);
    __half* s_b  = (__half*)(sm + OFF_B);
    __half* s_vt = (__half*)(sm + OFF_VT);

    int tid = threadIdx.x, wp = tid >> 5, lane = tid & 31;
    int g = lane >> 2, t = lane & 3;
    int n = blockIdx.x;
    int b = n / NWF;
    int w = g_sel[n];
    int wh = w >> 6, ww = w & 63;
    const size_t plane = (size_t)NH * NW;
    const float* fbase = fm  + (size_t)b*NC*plane + (size_t)(wh*8)*NW + ww*8;
    float*       obase = out + (size_t)b*NC*plane + (size_t)(wh*8)*NW + ww*8;

    // gather window (fp32 master + fp16 mirror) + stage k1 / v1t
    {
        int col = tid & 7, r = (tid >> 3) & 7, c0 = tid >> 6;
        int t8 = r*8 + col;
        #pragma unroll
        for (int k = 0; k < 32; k++) {
            int c = c0 + 4*k;
            float v = fbase[(size_t)c*plane + r*NW + col];
            s_wf[t8*WST + c] = v;
            s_a[t8*AST + c] = __float2half(v);
        }
        const uint4* kg = (const uint4*)(g_k16 + b*8192);
        const uint4* vg = (const uint4*)(g_v1t + b*8192);
        for (int i = tid; i < 1024; i += 256) {
            int row = i >> 4, c16 = i & 15;
            *(uint4*)(s_b + row*AST + c16*8) = kg[row*16 + c16];
        }
        for (int i = tid; i < 1024; i += 256) {
            int row = i >> 3, c8 = i & 7;
            *(uint4*)(s_vt + row*VST + c8*8) = vg[row*8 + c8];
        }
    }
    __syncthreads();

    float C[4][2][4];
    float Cq[4][4];

    // epilogue helpers as macros over fragment coords
    #define FOR_FRAG for (int mt = 0; mt < 4; mt++) for (int nt = 0; nt < 2; nt++)
    #define R0 (mt*16 + g)
    #define R1 (mt*16 + g + 8)
    #define CL (wp*16 + nt*8 + 2*t)

    // ---- q1 = wf @ Wqg^T ----
    gemmW(s_a, g_wfrag + MAT_QG*4096, lane, wp, C);
    __syncthreads();
    FOR_FRAG {
        *(uint32_t*)(s_a + R0*AST + CL) = h2u(C[mt][nt][0], C[mt][nt][1]);
        *(uint32_t*)(s_a + R1*AST + CL) = h2u(C[mt][nt][2], C[mt][nt][3]);
    }
    __syncthreads();

    // ---- logits1 = q1 @ k1^T ----
    gemmQK(s_a, s_b, lane, wp, Cq);
    #pragma unroll
    for (int mt = 0; mt < 4; mt++) {
        int cc = wp*8 + 2*t;
        s_p[(mt*16+g)*PST + cc]     = Cq[mt][0]*SCALE;
        s_p[(mt*16+g)*PST + cc+1]   = Cq[mt][1]*SCALE;
        s_p[(mt*16+g+8)*PST + cc]   = Cq[mt][2]*SCALE;
        s_p[(mt*16+g+8)*PST + cc+1] = Cq[mt][3]*SCALE;
    }
    __syncthreads();

    // ---- softmax (4 threads/row) -> s_a cols 0..63 as half ----
    {
        int row = tid >> 2, q = tid & 3;
        float* pr = s_p + row*PST + q*16;
        float m = -1e30f, v[16];
        #pragma unroll
        for (int k = 0; k < 16; k++) { v[k] = pr[k]; m = fmaxf(m, v[k]); }
        m = fmaxf(m, __shfl_xor_sync(0xffffffffu, m, 1));
        m = fmaxf(m, __shfl_xor_sync(0xffffffffu, m, 2));
        float s = 0.f;
        #pragma unroll
        for (int k = 0; k < 16; k++) { v[k] = __expf(v[k] - m); s += v[k]; }
        s += __shfl_xor_sync(0xffffffffu, s, 1);
        s += __shfl_xor_sync(0xffffffffu, s, 2);
        float inv = 1.0f / s;
        #pragma unroll
        for (int u = 0; u < 8; u++)
            *(uint32_t*)(s_a + row*AST + q*16 + 2*u) = h2u(v[2*u]*inv, v[2*u+1]*inv);
    }
    __syncthreads();

    // ---- av1 = attn @ v1 ; wf += av1 (refresh fp16 mirror) ----
    gemmAV(s_a, s_vt, lane, wp, C);
    __syncthreads();
    FOR_FRAG {
        float f0 = s_wf[R0*WST + CL]   + C[mt][nt][0];
        float f1 = s_wf[R0*WST + CL+1] + C[mt][nt][1];
        float f2 = s_wf[R1*WST + CL]   + C[mt][nt][2];
        float f3 = s_wf[R1*WST + CL+1] + C[mt][nt][3];
        s_wf[R0*WST + CL] = f0; s_wf[R0*WST + CL+1] = f1;
        s_wf[R1*WST + CL] = f2; s_wf[R1*WST + CL+1] = f3;
        *(uint32_t*)(s_a + R0*AST + CL) = h2u(f0, f1);
        *(uint32_t*)(s_a + R1*AST + CL) = h2u(f2, f3);
    }
    __syncthreads();

    // ---- MLP1: wf += gelu(wf @ lw^T + lb) ----
    gemmW(s_a, g_wfrag + MAT_LIN*4096, lane, wp, C);
    __syncthreads();
    FOR_FRAG {
        float b0 = __ldg(&lb[CL]), b1 = __ldg(&lb[CL+1]);
        float f0 = s_wf[R0*WST + CL]   + gelu_exact(C[mt][nt][0] + b0);
        float f1 = s_wf[R0*WST + CL+1] + gelu_exact(C[mt][nt][1] + b1);
        float f2 = s_wf[R1*WST + CL]   + gelu_exact(C[mt][nt][2] + b0);
        float f3 = s_wf[R1*WST + CL+1] + gelu_exact(C[mt][nt][3] + b1);
        s_wf[R0*WST + CL] = f0; s_wf[R0*WST + CL+1] = f1;
        s_wf[R1*WST + CL] = f2; s_wf[R1*WST + CL+1] = f3;
        *(uint32_t*)(s_a + R0*AST + CL) = h2u(f0, f1);
        *(uint32_t*)(s_a + R1*AST + CL) = h2u(f2, f3);
    }
    __syncthreads();

    // ---- self-attention: k2 -> s_b, v2 -> s_vt (transposed), q2 -> s_a ----
    gemmW(s_a, g_wfrag + MAT_K2*4096, lane, wp, C);
    FOR_FRAG {
        *(uint32_t*)(s_b + R0*AST + CL) = h2u(C[mt][nt][0], C[mt][nt][1]);
        *(uint32_t*)(s_b + R1*AST + CL) = h2u(C[mt][nt][2], C[mt][nt][3]);
    }
    gemmW(s_a, g_wfrag + MAT_V2*4096, lane, wp, C);
    FOR_FRAG {
        s_vt[(CL  )*VST + R0] = __float2half(C[mt][nt][0]);
        s_vt[(CL+1)*VST + R0] = __float2half(C[mt][nt][1]);
        s_vt[(CL  )*VST + R1] = __float2half(C[mt][nt][2]);
        s_vt[(CL+1)*VST + R1] = __float2half(C[mt][nt][3]);
    }
    gemmW(s_a, g_wfrag + MAT_Q2*4096, lane, wp, C);
    __syncthreads();
    FOR_FRAG {
        *(uint32_t*)(s_a + R0*AST + CL) = h2u(C[mt][nt][0], C[mt][nt][1]);
        *(uint32_t*)(s_a + R1*AST + CL) = h2u(C[mt][nt][2], C[mt][nt][3]);
    }
    __syncthreads();

    // ---- logits2 = q2 @ k2^T ----
    gemmQK(s_a, s_b, lane, wp, Cq);
    #pragma unroll
    for (int mt = 0; mt < 4; mt++) {
        int cc = wp*8 + 2*t;
        s_p[(mt*16+g)*PST + cc]     = Cq[mt][0]*SCALE;
        s_p[(mt*16+g)*PST + cc+1]   = Cq[mt][1]*SCALE;
        s_p[(mt*16+g+8)*PST + cc]   = Cq[mt][2]*SCALE;
        s_p[(mt*16+g+8)*PST + cc+1] = Cq[mt][3]*SCALE;
    }
    __syncthreads();
    {
        int row = tid >> 2, q = tid & 3;
        float* pr = s_p + row*PST + q*16;
        float m = -1e30f, v[16];
        #pragma unroll
        for (int k = 0; k < 16; k++) { v[k] = pr[k]; m = fmaxf(m, v[k]); }
        m = fmaxf(m, __shfl_xor_sync(0xffffffffu, m, 1));
        m = fmaxf(m, __shfl_xor_sync(0xffffffffu, m, 2));
        float s = 0.f;
        #pragma unroll
        for (int k = 0; k < 16; k++) { v[k] = __expf(v[k] - m); s += v[k]; }
        s += __shfl_xor_sync(0xffffffffu, s, 1);
        s += __shfl_xor_sync(0xffffffffu, s, 2);
        float inv = 1.0f / s;
        #pragma unroll
        for (int u = 0; u < 8; u++)
            *(uint32_t*)(s_a + row*AST + q*16 + 2*u) = h2u(v[2*u]*inv, v[2*u+1]*inv);
    }
    __syncthreads();

    // ---- av2 = attn @ v2 -> s_b (half) ----
    gemmAV(s_a, s_vt, lane, wp, C);
    FOR_FRAG {
        *(uint32_t*)(s_b + R0*AST + CL) = h2u(C[mt][nt][0], C[mt][nt][1]);
        *(uint32_t*)(s_b + R1*AST + CL) = h2u(C[mt][nt][2], C[mt][nt][3]);
    }
    __syncthreads();

    // ---- scrambled residual: wf[i][j] += av[j%64][2i + j/64] ----
    #pragma unroll
    for (int k = 0; k < 32; k++) {
        int idx = tid + 256*k;
        int i = idx >> 7, j = idx & 127;
        float f = s_wf[i*WST + j] + __half2float(s_b[(j & 63)*AST + 2*i + (j >> 6)]);
        s_wf[i*WST + j] = f;
        s_a[i*AST + j] = __float2half(f);
    }
    __syncthreads();

    // ---- MLP2: wf += gelu(wf @ pw^T + pb) ----
    gemmW(s_a, g_wfrag + MAT_PR*4096, lane, wp, C);
    __syncthreads();
    FOR_FRAG {
        float b0 = __ldg(&pb[CL]), b1 = __ldg(&pb[CL+1]);
        s_wf[R0*WST + CL]   += gelu_exact(C[mt][nt][0] + b0);
        s_wf[R0*WST + CL+1] += gelu_exact(C[mt][nt][1] + b1);
        s_wf[R1*WST + CL]   += gelu_exact(C[mt][nt][2] + b0);
        s_wf[R1*WST + CL+1] += gelu_exact(C[mt][nt][3] + b1);
    }
    __syncthreads();

    // ---- scatter ----
    {
        int col = tid & 7, r = (tid >> 3) & 7, c0 = tid >> 6;
        int t8 = r*8 + col;
        #pragma unroll
        for (int k = 0; k < 32; k++) {
            int c = c0 + 4*k;
            obase[(size_t)c*plane + r*NW + col] = s_wf[t8*WST + c];
        }
    }
    #undef FOR_FRAG
    #undef R0
    #undef R1
    #undef CL
}

// ---------------- launch ------------------------------------------------------
extern "C" void kernel_launch(void* const* d_in, const int* in_sizes, int n_in,
                              void* d_out, int out_size) {
    const float* fm   = (const float*)d_in[0];
    const float* unc  = (const float*)d_in[1];
    const float* qgw  = (const float*)d_in[2];
    const float* kvw  = (const float*)d_in[3];
    const float* lw   = (const float*)d_in[4];
    const float* lb   = (const float*)d_in[5];
    const float* qkvw = (const float*)d_in[6];
    const float* pw   = (const float*)d_in[7];
    const float* pb   = (const float*)d_in[8];
    float* out = (float*)d_out;

    cudaFuncSetAttribute(window_kernel,
                         cudaFuncAttributeMaxDynamicSharedMemorySize, SMEMB);

    wprep_kernel<<<96, 256>>>(qgw, lw, qkvw, pw);
    scores_kernel<<<1024, 256>>>(unc);
    select_kernel<<<8, 1024>>>();
    copy_pool_kernel<<<NB*NC*8, 512>>>(fm, out);
    kv_kernel<<<NB*64, 256>>>(kvw);
    window_kernel<<<NSEL, 256, SMEMB>>>(fm, lb, pb, out);
}